// round 14
// baseline (speedup 1.0000x reference)
#include <cuda_runtime.h>
#include <cstdint>

// CrfHead: out[b,t,:] = x[b,t,:] + transitions[argmax(x[b,t,:]), :]
// 131072 rows x 256 floats. One warp per row, Blackwell v8 (256-bit) memory
// ops, cache split (.cg stream in / .nc L1-resident transitions / .cs out).
// Tail shortened: argmax = REDUX.MAX on ordered key, then BALLOT+FFS+SHFL
// (lanes own ascending disjoint index ranges, so lowest lane holding the max
// key IS the first occurrence) instead of a second REDUX.

#define TAGS 256
#define ROWS (128 * 1024)
#define THREADS 512
#define WARPS_PER_BLOCK (THREADS / 32)
#define BLOCKS (ROWS / WARPS_PER_BLOCK)   // 8192

// Monotone float -> uint32 map (total order matches float <; no NaNs in input).
__device__ __forceinline__ unsigned ford(float f) {
    unsigned u = __float_as_uint(f);
    return (u >> 31) ? ~u : (u | 0x80000000u);
}

__device__ __forceinline__ void ldg_cg_v8(const float* p, float* v) {
    asm volatile("ld.global.cg.v8.f32 {%0,%1,%2,%3,%4,%5,%6,%7}, [%8];"
                 : "=f"(v[0]), "=f"(v[1]), "=f"(v[2]), "=f"(v[3]),
                   "=f"(v[4]), "=f"(v[5]), "=f"(v[6]), "=f"(v[7])
                 : "l"(p));
}

__device__ __forceinline__ void ldg_nc_v8(const float* p, float* v) {
    asm volatile("ld.global.nc.v8.f32 {%0,%1,%2,%3,%4,%5,%6,%7}, [%8];"
                 : "=f"(v[0]), "=f"(v[1]), "=f"(v[2]), "=f"(v[3]),
                   "=f"(v[4]), "=f"(v[5]), "=f"(v[6]), "=f"(v[7])
                 : "l"(p));
}

__device__ __forceinline__ void stg_cs_v8(float* p, const float* v) {
    asm volatile("st.global.cs.v8.f32 [%0], {%1,%2,%3,%4,%5,%6,%7,%8};"
                 :: "l"(p),
                    "f"(v[0]), "f"(v[1]), "f"(v[2]), "f"(v[3]),
                    "f"(v[4]), "f"(v[5]), "f"(v[6]), "f"(v[7])
                 : "memory");
}

__global__ __launch_bounds__(THREADS, 4)
void crf_head_kernel(const float* __restrict__ x,
                     const float* __restrict__ trans,
                     float* __restrict__ out) {
    const int warp = (blockIdx.x * THREADS + threadIdx.x) >> 5;
    const int lane = threadIdx.x & 31;

    // Lane owns 8 contiguous elements: [lane*8, lane*8+8).
    const size_t base = (size_t)warp * TAGS + lane * 8;

    float a[8];
    ldg_cg_v8(&x[base], a);   // single 256-bit streaming load (L2 only)

    // Lane-local argmax; strict > keeps lowest index-within-lane.
    float v = a[0]; int idx = lane * 8;
    #pragma unroll
    for (int e = 1; e < 8; e++)
        if (a[e] > v) { v = a[e]; idx = lane * 8 + e; }

    // Warp argmax: REDUX.MAX on ordered key; first occurrence = lowest lane
    // holding the max (lane index ranges are ascending and disjoint).
    const unsigned k = ford(v);
    const unsigned m = __reduce_max_sync(0xFFFFFFFFu, k);
    const unsigned holders = __ballot_sync(0xFFFFFFFFu, k == m);
    const int src = __ffs(holders) - 1;
    const int best = __shfl_sync(0xFFFFFFFFu, idx, src);

    // transitions row: 256KB working set, L1-resident via nc path.
    float t[8];
    ldg_nc_v8(&trans[(size_t)best * TAGS + lane * 8], t);

    float r[8];
    #pragma unroll
    for (int e = 0; e < 8; e++) r[e] = a[e] + t[e];

    stg_cs_v8(&out[base], r); // single 256-bit streaming store
}

extern "C" void kernel_launch(void* const* d_in, const int* in_sizes, int n_in,
                              void* d_out, int out_size) {
    const float* x     = reinterpret_cast<const float*>(d_in[0]);
    const float* trans = reinterpret_cast<const float*>(d_in[1]);
    float*       out   = reinterpret_cast<float*>(d_out);

    crf_head_kernel<<<BLOCKS, THREADS>>>(x, trans, out);
}